// round 1
// baseline (speedup 1.0000x reference)
#include <cuda_runtime.h>

// Problem constants (fixed by the reference)
#define LP    4
#define ENC   32
#define FEAT  64
#define D3    64
#define NROWS (512 * 2048)   // B * M = 1,048,576

typedef unsigned long long u64;

// Folded weights: A = W2 @ Wm1[:ENC]  (32x64), ybias = bm1 + b2 @ Wm1[:ENC]
__device__ float g_A[ENC * D3];
__device__ float g_ybias[D3];

__device__ __forceinline__ u64 pack2(float lo, float hi) {
    u64 r;
    asm("mov.b64 %0, {%1, %2};" : "=l"(r) : "f"(lo), "f"(hi));
    return r;
}
__device__ __forceinline__ void unpack2(float& lo, float& hi, u64 v) {
    asm("mov.b64 {%0, %1}, %2;" : "=f"(lo), "=f"(hi) : "l"(v));
}
__device__ __forceinline__ u64 ffma2(u64 a, u64 b, u64 c) {
    u64 d;
    asm("fma.rn.f32x2 %0, %1, %2, %3;" : "=l"(d) : "l"(a), "l"(b), "l"(c));
    return d;
}

// ---------------------------------------------------------------------------
// Prep: fold W2 into the pe-half of Wm1 (runs every launch; deterministic).
// ---------------------------------------------------------------------------
__global__ void prep_kernel(const float* __restrict__ W2,
                            const float* __restrict__ Wm1,
                            const float* __restrict__ b2,
                            const float* __restrict__ bm1) {
    int t = blockIdx.x * blockDim.x + threadIdx.x;
    if (t < ENC * D3) {
        int k = t >> 6;        // row of A (ENC)
        int j = t & 63;        // col of A (D3)
        float s = 0.f;
        #pragma unroll
        for (int e = 0; e < ENC; e++)
            s = fmaf(W2[k * ENC + e], Wm1[e * D3 + j], s);
        g_A[t] = s;
    }
    if (t < D3) {
        float s = bm1[t];
        #pragma unroll
        for (int e = 0; e < ENC; e++)
            s = fmaf(b2[e], Wm1[e * D3 + t], s);
        g_ybias[t] = s;
    }
}

// ---------------------------------------------------------------------------
// Main: one thread per output row. fp32x2-packed FMAs, weights in smem.
// ---------------------------------------------------------------------------
__global__ __launch_bounds__(128)
void neurtw_kernel(const float* __restrict__ pos_table,
                   const float* __restrict__ node_feat,
                   const float* __restrict__ W1,
                   const float* __restrict__ b1,
                   const float* __restrict__ Wm1,   // use rows [ENC, ENC+FEAT)
                   const float* __restrict__ Wm2,
                   const float* __restrict__ bm2,
                   const int*   __restrict__ key_idx,
                   const int*   __restrict__ node_idx,
                   float* __restrict__ out,
                   int nrows) {
    __shared__ float sW1[LP * ENC];
    __shared__ float sb1[ENC];
    __shared__ __align__(16) u64 sA[ENC * D3 / 2];    // A as packed f32x2 pairs
    __shared__ __align__(16) u64 sB[FEAT * D3 / 2];   // Wm1 feat-half, packed pairs
    __shared__ __align__(16) u64 sYb[D3 / 2];
    __shared__ float sWm2[D3];
    __shared__ float sbm2;

    const int tid = threadIdx.x;
    const int nthr = blockDim.x;

    for (int i = tid; i < LP * ENC; i += nthr) sW1[i] = W1[i];
    for (int i = tid; i < ENC; i += nthr)      sb1[i] = b1[i];
    {
        const float2* A2 = (const float2*)g_A;
        for (int i = tid; i < ENC * D3 / 2; i += nthr) {
            float2 v = A2[i];
            sA[i] = pack2(v.x, v.y);
        }
        const float2* B2 = (const float2*)(Wm1 + ENC * D3);
        for (int i = tid; i < FEAT * D3 / 2; i += nthr) {
            float2 v = B2[i];
            sB[i] = pack2(v.x, v.y);
        }
        const float2* Y2 = (const float2*)g_ybias;
        for (int i = tid; i < D3 / 2; i += nthr) {
            float2 v = Y2[i];
            sYb[i] = pack2(v.x, v.y);
        }
    }
    for (int i = tid; i < D3; i += nthr) sWm2[i] = Wm2[i];
    if (tid == 0) sbm2 = bm2[0];
    __syncthreads();

    const int row = blockIdx.x * nthr + tid;
    if (row >= nrows) return;

    const int key = key_idx[row];
    const int nid = node_idx[row];

    // ---- Position encoding hidden layer: h = relu(enc @ W1 + b1) ----
    const float4 e4 = *(const float4*)(pos_table + (size_t)key * LP);
    float h[ENC];
    #pragma unroll
    for (int j = 0; j < ENC; j++) {
        float s = sb1[j];
        s = fmaf(e4.x, sW1[0 * ENC + j], s);
        s = fmaf(e4.y, sW1[1 * ENC + j], s);
        s = fmaf(e4.z, sW1[2 * ENC + j], s);
        s = fmaf(e4.w, sW1[3 * ENC + j], s);
        h[j] = fmaxf(s, 0.f);
    }

    // ---- y = ybias + relu(h) @ A + feat @ B  (64-wide, packed as 32 f32x2) ----
    u64 y[D3 / 2];
    #pragma unroll
    for (int p = 0; p < D3 / 2; p++) y[p] = sYb[p];

    #pragma unroll
    for (int k = 0; k < ENC; k++) {
        const u64 x2 = pack2(h[k], h[k]);
        const u64* wrow = &sA[k * (D3 / 2)];
        #pragma unroll
        for (int p = 0; p < D3 / 2; p++)
            y[p] = ffma2(x2, wrow[p], y[p]);
    }

    const float4* f4p = (const float4*)(node_feat + (size_t)nid * FEAT);
    #pragma unroll
    for (int kk = 0; kk < FEAT / 4; kk++) {
        const float4 f = __ldg(&f4p[kk]);
        const float fv[4] = {f.x, f.y, f.z, f.w};
        #pragma unroll
        for (int u = 0; u < 4; u++) {
            const int k = kk * 4 + u;
            const u64 x2 = pack2(fv[u], fv[u]);
            const u64* wrow = &sB[k * (D3 / 2)];
            #pragma unroll
            for (int p = 0; p < D3 / 2; p++)
                y[p] = ffma2(x2, wrow[p], y[p]);
        }
    }

    // ---- z = relu(y) @ Wm2 + bm2 ----
    float z = sbm2;
    #pragma unroll
    for (int p = 0; p < D3 / 2; p++) {
        float lo, hi;
        unpack2(lo, hi, y[p]);
        z = fmaf(fmaxf(lo, 0.f), sWm2[2 * p],     z);
        z = fmaf(fmaxf(hi, 0.f), sWm2[2 * p + 1], z);
    }
    out[row] = z;
}

extern "C" void kernel_launch(void* const* d_in, const int* in_sizes, int n_in,
                              void* d_out, int out_size) {
    const float* pos_table = (const float*)d_in[0];
    const float* node_feat = (const float*)d_in[1];
    const float* W1        = (const float*)d_in[2];
    const float* b1        = (const float*)d_in[3];
    const float* W2        = (const float*)d_in[4];
    const float* b2        = (const float*)d_in[5];
    const float* Wm1       = (const float*)d_in[6];
    const float* bm1       = (const float*)d_in[7];
    const float* Wm2       = (const float*)d_in[8];
    const float* bm2       = (const float*)d_in[9];
    const int*   key_idx   = (const int*)d_in[10];
    const int*   node_idx  = (const int*)d_in[11];
    float* out = (float*)d_out;

    const int nrows = out_size;  // B*M*1

    prep_kernel<<<(ENC * D3 + 255) / 256, 256>>>(W2, Wm1, b2, bm1);

    const int threads = 128;
    const int blocks = (nrows + threads - 1) / threads;
    neurtw_kernel<<<blocks, threads>>>(pos_table, node_feat, W1, b1, Wm1,
                                       Wm2, bm2, key_idx, node_idx, out, nrows);
}

// round 2
// speedup vs baseline: 1.3386x; 1.3386x over previous
#include <cuda_runtime.h>

#define LP    4
#define ENC   32
#define FEAT  64
#define KTOT  (ENC + FEAT)   // 96
#define D3    64
#define TM    128            // rows per block

typedef unsigned long long u64;

// Folded weights: g_A = W2 @ Wm1[:ENC]  (32x64), g_ybias = bm1 + b2 @ Wm1[:ENC]
__device__ float g_A[ENC * D3];
__device__ float g_ybias[D3];

__device__ __forceinline__ u64 pack2(float lo, float hi) {
    u64 r;
    asm("mov.b64 %0, {%1, %2};" : "=l"(r) : "f"(lo), "f"(hi));
    return r;
}
__device__ __forceinline__ void unpack2(float& lo, float& hi, u64 v) {
    asm("mov.b64 {%0, %1}, %2;" : "=f"(lo), "=f"(hi) : "l"(v));
}
__device__ __forceinline__ u64 ffma2(u64 a, u64 b, u64 c) {
    u64 d;
    asm("fma.rn.f32x2 %0, %1, %2, %3;" : "=l"(d) : "l"(a), "l"(b), "l"(c));
    return d;
}

// ---------------------------------------------------------------------------
__global__ void prep_kernel(const float* __restrict__ W2,
                            const float* __restrict__ Wm1,
                            const float* __restrict__ b2,
                            const float* __restrict__ bm1) {
    int t = blockIdx.x * blockDim.x + threadIdx.x;
    if (t < ENC * D3) {
        int k = t >> 6, j = t & 63;
        float s = 0.f;
        #pragma unroll
        for (int e = 0; e < ENC; e++)
            s = fmaf(W2[k * ENC + e], Wm1[e * D3 + j], s);
        g_A[t] = s;
    }
    if (t < D3) {
        float s = bm1[t];
        #pragma unroll
        for (int e = 0; e < ENC; e++)
            s = fmaf(b2[e], Wm1[e * D3 + t], s);
        g_ybias[t] = s;
    }
}

// ---------------------------------------------------------------------------
// Block: 128 threads, 128 rows.
// Phase 1: gather + PE-MLP, stage X[96][128] and W[96][32 pairs] in smem.
// Phase 2: register-tiled GEMM: thread (ty,tx) -> rows ty*8..+7, col-pairs tx*4..+3.
// Phase 3: relu -> dot Wm2 partials -> shfl-xor reduce over 8 tx lanes -> store.
// ---------------------------------------------------------------------------
// smem layout (bytes):
//   Xs   : 96*128 f32         = 49152
//   sWp  : 96*32  u64 pairs   = 24576
//   sW1  : 128 f32, sb1: 32 f32
//   sYbp : 32 u64, sWm2p: 32 u64, sbm2: f32
#define SMEM_XS    0
#define SMEM_WP    49152
#define SMEM_W1    (SMEM_WP + 24576)
#define SMEM_B1    (SMEM_W1 + 128 * 4)
#define SMEM_YB    (SMEM_B1 + 32 * 4)
#define SMEM_WM2   (SMEM_YB + 32 * 8)
#define SMEM_BM2   (SMEM_WM2 + 32 * 8)
#define SMEM_TOTAL (SMEM_BM2 + 16)

__global__ __launch_bounds__(128, 3)
void neurtw_kernel(const float* __restrict__ pos_table,
                   const float* __restrict__ node_feat,
                   const float* __restrict__ W1,
                   const float* __restrict__ b1,
                   const float* __restrict__ Wm1,   // bottom rows [ENC, KTOT)
                   const float* __restrict__ Wm2,
                   const float* __restrict__ bm2,
                   const int*   __restrict__ key_idx,
                   const int*   __restrict__ node_idx,
                   float* __restrict__ out,
                   int nrows) {
    extern __shared__ char smem[];
    float* Xs    = (float*)(smem + SMEM_XS);    // [96][128]
    u64*   sWp   = (u64*)  (smem + SMEM_WP);    // [96][32] col-pairs
    float* sW1   = (float*)(smem + SMEM_W1);
    float* sb1   = (float*)(smem + SMEM_B1);
    u64*   sYbp  = (u64*)  (smem + SMEM_YB);
    u64*   sWm2p = (u64*)  (smem + SMEM_WM2);
    float* sbm2  = (float*)(smem + SMEM_BM2);

    const int tid = threadIdx.x;
    const int base = blockIdx.x * TM;
    const int row = base + tid;

    // ---- small params ----
    if (tid < 128) sW1[tid] = W1[tid];
    if (tid < 32)  sb1[tid] = b1[tid];
    if (tid >= 32 && tid < 64) {
        int p = tid - 32;
        sYbp[p] = pack2(g_ybias[2 * p], g_ybias[2 * p + 1]);
    }
    if (tid >= 64 && tid < 96) {
        int p = tid - 64;
        sWm2p[p] = pack2(Wm2[2 * p], Wm2[2 * p + 1]);
    }
    if (tid == 96) *sbm2 = bm2[0];

    // ---- weight tile: rows 0..31 from g_A, 32..95 from Wm1 bottom ----
    // 96*32 = 3072 u64 pairs; 24 per thread.
    #pragma unroll
    for (int i = 0; i < 24; i++) {
        int t = i * 128 + tid;           // pair index
        int k = t >> 5;                  // weight row 0..95
        int p = t & 31;                  // col pair 0..31
        const float* src = (k < ENC) ? (g_A + k * D3) : (Wm1 + k * D3); // k>=32: Wm1[(k-32+ENC)*D3] = Wm1[k*D3]
        float2 v = *(const float2*)(src + 2 * p);
        sWp[t] = pack2(v.x, v.y);
    }

    // ---- gather + PE hidden layer for this thread's row ----
    bool valid = (row < nrows);
    int key = 0, nid = 0;
    if (valid) { key = key_idx[row]; nid = node_idx[row]; }

    float4 e4 = make_float4(0.f, 0.f, 0.f, 0.f);
    if (valid) e4 = *(const float4*)(pos_table + (size_t)key * LP);

    // feat loads issued early for latency overlap
    float4 f[16];
    const float4* f4p = (const float4*)(node_feat + (size_t)nid * FEAT);
    #pragma unroll
    for (int i = 0; i < 16; i++) f[i] = valid ? __ldg(&f4p[i]) : make_float4(0.f,0.f,0.f,0.f);

    #pragma unroll
    for (int j = 0; j < ENC; j++) {
        float s = sb1[j];
        s = fmaf(e4.x, sW1[0 * ENC + j], s);
        s = fmaf(e4.y, sW1[1 * ENC + j], s);
        s = fmaf(e4.z, sW1[2 * ENC + j], s);
        s = fmaf(e4.w, sW1[3 * ENC + j], s);
        Xs[j * TM + tid] = fmaxf(s, 0.f);
    }
    #pragma unroll
    for (int i = 0; i < 16; i++) {
        Xs[(ENC + 4 * i + 0) * TM + tid] = f[i].x;
        Xs[(ENC + 4 * i + 1) * TM + tid] = f[i].y;
        Xs[(ENC + 4 * i + 2) * TM + tid] = f[i].z;
        Xs[(ENC + 4 * i + 3) * TM + tid] = f[i].w;
    }
    __syncthreads();

    // ---- phase 2: register-tiled GEMM ----
    const int tx = tid & 7;          // col group: pairs tx*4 .. tx*4+3
    const int ty = tid >> 3;         // row group: rows ty*8 .. ty*8+7

    u64 y[8][4];
    {
        u64 yb0 = sYbp[tx * 4 + 0], yb1 = sYbp[tx * 4 + 1];
        u64 yb2 = sYbp[tx * 4 + 2], yb3 = sYbp[tx * 4 + 3];
        #pragma unroll
        for (int r = 0; r < 8; r++) {
            y[r][0] = yb0; y[r][1] = yb1; y[r][2] = yb2; y[r][3] = yb3;
        }
    }

    const float4* xrow0 = (const float4*)(Xs) + ty * 2;      // advance by 32 float4 per k
    const u64* wrow0 = sWp + tx * 4;                          // advance by 32 u64 per k

    #pragma unroll 8
    for (int k = 0; k < KTOT; k++) {
        const float4 xa = xrow0[k * 32 + 0];
        const float4 xb = xrow0[k * 32 + 1];
        u64 w0, w1, w2, w3;
        {
            const u64* w = wrow0 + k * 32;
            w0 = w[0]; w1 = w[1]; w2 = w[2]; w3 = w[3];
        }
        const float xv[8] = {xa.x, xa.y, xa.z, xa.w, xb.x, xb.y, xb.z, xb.w};
        #pragma unroll
        for (int r = 0; r < 8; r++) {
            const u64 x2 = pack2(xv[r], xv[r]);
            y[r][0] = ffma2(x2, w0, y[r][0]);
            y[r][1] = ffma2(x2, w1, y[r][1]);
            y[r][2] = ffma2(x2, w2, y[r][2]);
            y[r][3] = ffma2(x2, w3, y[r][3]);
        }
    }

    // ---- phase 3: relu -> Wm2 partial dot -> reduce over tx lanes ----
    float wlo[4], whi[4];
    #pragma unroll
    for (int c = 0; c < 4; c++) unpack2(wlo[c], whi[c], sWm2p[tx * 4 + c]);

    float part[8];
    #pragma unroll
    for (int r = 0; r < 8; r++) {
        float z = 0.f;
        #pragma unroll
        for (int c = 0; c < 4; c++) {
            float lo, hi;
            unpack2(lo, hi, y[r][c]);
            z = fmaf(fmaxf(lo, 0.f), wlo[c], z);
            z = fmaf(fmaxf(hi, 0.f), whi[c], z);
        }
        part[r] = z;
    }
    #pragma unroll
    for (int o = 1; o < 8; o <<= 1) {
        #pragma unroll
        for (int r = 0; r < 8; r++)
            part[r] += __shfl_xor_sync(0xffffffffu, part[r], o);
    }
    if (tx == 0) {
        const float bias = *sbm2;
        const int orow = base + ty * 8;
        #pragma unroll
        for (int r = 0; r < 8; r++)
            if (orow + r < nrows) out[orow + r] = part[r] + bias;
    }
}

extern "C" void kernel_launch(void* const* d_in, const int* in_sizes, int n_in,
                              void* d_out, int out_size) {
    const float* pos_table = (const float*)d_in[0];
    const float* node_feat = (const float*)d_in[1];
    const float* W1        = (const float*)d_in[2];
    const float* b1        = (const float*)d_in[3];
    const float* W2        = (const float*)d_in[4];
    const float* b2        = (const float*)d_in[5];
    const float* Wm1       = (const float*)d_in[6];
    const float* bm1       = (const float*)d_in[7];
    const float* Wm2       = (const float*)d_in[8];
    const float* bm2       = (const float*)d_in[9];
    const int*   key_idx   = (const int*)d_in[10];
    const int*   node_idx  = (const int*)d_in[11];
    float* out = (float*)d_out;

    const int nrows = out_size;

    static int configured = 0;
    if (!configured) {
        cudaFuncSetAttribute(neurtw_kernel,
                             cudaFuncAttributeMaxDynamicSharedMemorySize, SMEM_TOTAL);
        configured = 1;
    }

    prep_kernel<<<(ENC * D3 + 255) / 256, 256>>>(W2, Wm1, b2, bm1);

    const int blocks = (nrows + TM - 1) / TM;
    neurtw_kernel<<<blocks, 128, SMEM_TOTAL>>>(pos_table, node_feat, W1, b1, Wm1,
                                               Wm2, bm2, key_idx, node_idx, out, nrows);
}

// round 4
// speedup vs baseline: 1.8535x; 1.3846x over previous
#include <cuda_runtime.h>
#include <cuda_bf16.h>
#include <stdint.h>

#define LP    4
#define ENC   32
#define FEAT  64
#define D3    64
#define NBLK  296
#define WARPS_PER_BLK 4

// X rows: 96 bf16 data + pad -> stride 104 bf16 = 208 B (52 words; 52*r mod 32 distinct for r=0..7)
#define XSTRIDE_B 208
// W rows: 64 bf16 data + pad -> stride 72 bf16 = 144 B (36 words; 36*r mod 32 distinct)
#define WSTRIDE_B 144

// ---- smem layout (bytes) ----
#define OFF_W1   0                    // 128 f32
#define OFF_B1   512                  // 32 f32
#define OFF_YB   640                  // 64 f32
#define OFF_WM2  896                  // 64 f32
#define OFF_BM2  1152                 // 1 f32
#define OFF_WH   1280                 // 96 rows * 144 B = 13824
#define OFF_WL   (OFF_WH + 96 * WSTRIDE_B)
#define OFF_XH   (OFF_WL + 96 * WSTRIDE_B)          // 128 rows * 208 B = 26624
#define OFF_XL   (OFF_XH + 128 * XSTRIDE_B)
#define SMEM_TOTAL (OFF_XL + 128 * XSTRIDE_B)       // ~82 KB

__device__ float g_A[ENC * D3];
__device__ float g_ybias[D3];

// ---------------- helpers ----------------
__device__ __forceinline__ uint32_t smem_u32(const void* p) {
    uint32_t a;
    asm("{ .reg .u64 t; cvta.to.shared.u64 t, %1; cvt.u32.u64 %0, t; }" : "=r"(a) : "l"(p));
    return a;
}
#define LDSM_X4(r0, r1, r2, r3, a) \
    asm volatile("ldmatrix.sync.aligned.m8n8.x4.shared.b16 {%0,%1,%2,%3}, [%4];" \
                 : "=r"(r0), "=r"(r1), "=r"(r2), "=r"(r3) : "r"(a))
#define LDSM_X4_T(r0, r1, r2, r3, a) \
    asm volatile("ldmatrix.sync.aligned.m8n8.x4.trans.shared.b16 {%0,%1,%2,%3}, [%4];" \
                 : "=r"(r0), "=r"(r1), "=r"(r2), "=r"(r3) : "r"(a))
#define MMA16816(d, a0, a1, a2, a3, b0, b1) \
    asm volatile("mma.sync.aligned.m16n8k16.row.col.f32.bf16.bf16.f32 " \
                 "{%0,%1,%2,%3}, {%4,%5,%6,%7}, {%8,%9}, {%0,%1,%2,%3};" \
                 : "+f"((d)[0]), "+f"((d)[1]), "+f"((d)[2]), "+f"((d)[3]) \
                 : "r"(a0), "r"(a1), "r"(a2), "r"(a3), "r"(b0), "r"(b1))

__device__ __forceinline__ unsigned pack_bf2(__nv_bfloat16 lo, __nv_bfloat16 hi) {
    return (unsigned)__bfloat16_as_ushort(lo) | ((unsigned)__bfloat16_as_ushort(hi) << 16);
}
__device__ __forceinline__ void split_bf(float x, __nv_bfloat16& h, __nv_bfloat16& l) {
    h = __float2bfloat16_rn(x);
    l = __float2bfloat16_rn(x - __bfloat162float(h));
}

// ---------------------------------------------------------------------------
__global__ void prep_kernel(const float* __restrict__ W2,
                            const float* __restrict__ Wm1,
                            const float* __restrict__ b2,
                            const float* __restrict__ bm1) {
    int t = blockIdx.x * blockDim.x + threadIdx.x;
    if (t < ENC * D3) {
        int k = t >> 6, j = t & 63;
        float s = 0.f;
        #pragma unroll
        for (int e = 0; e < ENC; e++)
            s = fmaf(W2[k * ENC + e], Wm1[e * D3 + j], s);
        g_A[t] = s;
    }
    if (t < D3) {
        float s = bm1[t];
        #pragma unroll
        for (int e = 0; e < ENC; e++)
            s = fmaf(b2[e], Wm1[e * D3 + t], s);
        g_ybias[t] = s;
    }
}

// ---------------------------------------------------------------------------
__global__ __launch_bounds__(128, 2)
void neurtw_mma(const float* __restrict__ pos_table,
                const float* __restrict__ node_feat,
                const float* __restrict__ W1,
                const float* __restrict__ b1,
                const float* __restrict__ Wm1,
                const float* __restrict__ Wm2,
                const float* __restrict__ bm2,
                const int*   __restrict__ key_idx,
                const int*   __restrict__ node_idx,
                float* __restrict__ out,
                int nrows, int ntiles) {
    extern __shared__ __align__(128) char smem[];
    const uint32_t sb = smem_u32(smem);
    const int tid = threadIdx.x, wid = tid >> 5, lane = tid & 31;

    float* sW1  = (float*)(smem + OFF_W1);
    float* sb1a = (float*)(smem + OFF_B1);
    float* sYb  = (float*)(smem + OFF_YB);
    float* sWm2 = (float*)(smem + OFF_WM2);
    float* sbm2 = (float*)(smem + OFF_BM2);

    if (tid < 128) sW1[tid] = W1[tid];
    if (tid < 32)  sb1a[tid] = b1[tid];
    if (tid < 64)  { sYb[tid] = g_ybias[tid]; sWm2[tid] = Wm2[tid]; }
    if (tid == 0)  *sbm2 = bm2[0];

    // stage W (hi/lo split) once: rows 0..31 from g_A, 32..95 from Wm1
    for (int t = tid; t < 96 * 64; t += 128) {
        int k = t >> 6, n = t & 63;
        float w = (k < ENC) ? g_A[k * D3 + n] : Wm1[k * D3 + n];
        __nv_bfloat16 h, l;
        split_bf(w, h, l);
        *(__nv_bfloat16*)(smem + OFF_WH + k * WSTRIDE_B + n * 2) = h;
        *(__nv_bfloat16*)(smem + OFF_WL + k * WSTRIDE_B + n * 2) = l;
    }
    __syncthreads();

    // per-lane ldmatrix address offsets (constant)
    // A x4 (non-trans): matrix = lane>>3; row = (lane&7) + 8*((lane>>3)&1); colgrp = lane>>4
    const int a_row = (lane & 7) + 8 * ((lane >> 3) & 1);
    const int a_colb = (lane >> 4) * 16;               // bytes (8 bf16)
    // B x4 trans on W[k][n]: row k-offset = (lane&7) + 8*((lane>>3)&1); n-offset = 8*(lane>>4)
    const uint32_t b_off = (uint32_t)(((lane & 7) + 8 * ((lane >> 3) & 1)) * WSTRIDE_B
                                      + (lane >> 4) * 8 * 2);

    const uint32_t xh_base = sb + OFF_XH + (uint32_t)(wid * 32 + a_row) * XSTRIDE_B + a_colb;
    const uint32_t xl_base = sb + OFF_XL + (uint32_t)(wid * 32 + a_row) * XSTRIDE_B + a_colb;
    const uint32_t wh_base = sb + OFF_WH + b_off;
    const uint32_t wl_base = sb + OFF_WL + b_off;

    // STS pointers for this thread's row (tid = row within block tile)
    uint4* xh_row = (uint4*)(smem + OFF_XH + tid * XSTRIDE_B);
    uint4* xl_row = (uint4*)(smem + OFF_XL + tid * XSTRIDE_B);

    const int gw0 = blockIdx.x * WARPS_PER_BLK + wid;   // global warp id
    const int gwstride = NBLK * WARPS_PER_BLK;

    // ---- prefetch first tile's gathers ----
    float4 e4 = make_float4(0.f, 0.f, 0.f, 0.f);
    float4 f[16];
    #pragma unroll
    for (int i = 0; i < 16; i++) f[i] = make_float4(0.f, 0.f, 0.f, 0.f);
    if (gw0 < ntiles) {
        int rr = gw0 * 32 + lane; if (rr >= nrows) rr = 0;
        int key = key_idx[rr], nid = node_idx[rr];
        e4 = *(const float4*)(pos_table + (size_t)key * LP);
        const float4* fp = (const float4*)(node_feat + (size_t)nid * FEAT);
        #pragma unroll
        for (int i = 0; i < 16; i++) f[i] = __ldg(fp + i);
    }

    const int g = lane >> 2, q = lane & 3;
    const float yb0[2] = {0.f, 0.f}; (void)yb0;

    for (int tile = gw0; tile < ntiles; tile += gwstride) {
        // ---- phase 1: PE hidden layer + split + STS (this warp's 32 rows) ----
        unsigned c_h[48], c_l[48];
        {
            float h[ENC];
            #pragma unroll
            for (int j = 0; j < ENC; j++) {
                float s = sb1a[j];
                s = fmaf(e4.x, sW1[0 * ENC + j], s);
                s = fmaf(e4.y, sW1[1 * ENC + j], s);
                s = fmaf(e4.z, sW1[2 * ENC + j], s);
                s = fmaf(e4.w, sW1[3 * ENC + j], s);
                h[j] = fmaxf(s, 0.f);
            }
            #pragma unroll
            for (int j = 0; j < ENC; j += 2) {
                __nv_bfloat16 a0, l0, a1, l1;
                split_bf(h[j], a0, l0); split_bf(h[j + 1], a1, l1);
                c_h[j >> 1] = pack_bf2(a0, a1);
                c_l[j >> 1] = pack_bf2(l0, l1);
            }
            #pragma unroll
            for (int i = 0; i < 16; i++) {
                __nv_bfloat16 a0, l0, a1, l1;
                split_bf(f[i].x, a0, l0); split_bf(f[i].y, a1, l1);
                c_h[16 + 2 * i] = pack_bf2(a0, a1);
                c_l[16 + 2 * i] = pack_bf2(l0, l1);
                split_bf(f[i].z, a0, l0); split_bf(f[i].w, a1, l1);
                c_h[16 + 2 * i + 1] = pack_bf2(a0, a1);
                c_l[16 + 2 * i + 1] = pack_bf2(l0, l1);
            }
        }
        #pragma unroll
        for (int p = 0; p < 12; p++) {
            xh_row[p] = make_uint4(c_h[4*p], c_h[4*p+1], c_h[4*p+2], c_h[4*p+3]);
            xl_row[p] = make_uint4(c_l[4*p], c_l[4*p+1], c_l[4*p+2], c_l[4*p+3]);
        }
        __syncwarp();

        // ---- prefetch next tile's gathers (in flight during MMA) ----
        {
            int nt = tile + gwstride;
            if (nt < ntiles) {
                int rr = nt * 32 + lane; if (rr >= nrows) rr = 0;
                int key = key_idx[rr], nid = node_idx[rr];
                e4 = *(const float4*)(pos_table + (size_t)key * LP);
                const float4* fp = (const float4*)(node_feat + (size_t)nid * FEAT);
                #pragma unroll
                for (int i = 0; i < 16; i++) f[i] = __ldg(fp + i);
            }
        }

        // ---- phase 2: 3-pass split-bf16 MMA ----
        float acc[2][8][4];
        #pragma unroll
        for (int mt = 0; mt < 2; mt++)
            #pragma unroll
            for (int nt = 0; nt < 8; nt++)
                #pragma unroll
                for (int c = 0; c < 4; c++) acc[mt][nt][c] = 0.f;

        #pragma unroll
        for (int kc = 0; kc < 6; kc++) {
            const uint32_t akoff = (uint32_t)(kc * 32);     // 16 bf16 = 32 B
            const uint32_t bkoff = (uint32_t)(kc * 16 * WSTRIDE_B);
            uint32_t ah[2][4], al[2][4];
            LDSM_X4(ah[0][0], ah[0][1], ah[0][2], ah[0][3], xh_base + akoff);
            LDSM_X4(ah[1][0], ah[1][1], ah[1][2], ah[1][3], xh_base + 16 * XSTRIDE_B + akoff);
            LDSM_X4(al[0][0], al[0][1], al[0][2], al[0][3], xl_base + akoff);
            LDSM_X4(al[1][0], al[1][1], al[1][2], al[1][3], xl_base + 16 * XSTRIDE_B + akoff);

            uint32_t bh[8][2], bl[8][2];
            #pragma unroll
            for (int ng = 0; ng < 4; ng++) {
                uint32_t r0, r1, r2, r3;
                LDSM_X4_T(r0, r1, r2, r3, wh_base + bkoff + (uint32_t)(ng * 32));  // 16 cols = 32 B
                bh[2*ng][0] = r0; bh[2*ng][1] = r1; bh[2*ng+1][0] = r2; bh[2*ng+1][1] = r3;
                LDSM_X4_T(r0, r1, r2, r3, wl_base + bkoff + (uint32_t)(ng * 32));
                bl[2*ng][0] = r0; bl[2*ng][1] = r1; bl[2*ng+1][0] = r2; bl[2*ng+1][1] = r3;
            }
            #pragma unroll
            for (int mt = 0; mt < 2; mt++) {
                #pragma unroll
                for (int nt = 0; nt < 8; nt++) {
                    MMA16816(acc[mt][nt], ah[mt][0], ah[mt][1], ah[mt][2], ah[mt][3],
                             bh[nt][0], bh[nt][1]);
                    MMA16816(acc[mt][nt], ah[mt][0], ah[mt][1], ah[mt][2], ah[mt][3],
                             bl[nt][0], bl[nt][1]);
                    MMA16816(acc[mt][nt], al[mt][0], al[mt][1], al[mt][2], al[mt][3],
                             bh[nt][0], bh[nt][1]);
                }
            }
        }

        // ---- phase 3: bias + relu + Wm2 dot + lane reduce + store ----
        float zr[4] = {0.f, 0.f, 0.f, 0.f};
        #pragma unroll
        for (int mt = 0; mt < 2; mt++) {
            #pragma unroll
            for (int nt = 0; nt < 8; nt++) {
                const int c0 = nt * 8 + 2 * q;
                const float y0 = sYb[c0], y1 = sYb[c0 + 1];
                const float w0 = sWm2[c0], w1 = sWm2[c0 + 1];
                zr[mt*2+0] = fmaf(fmaxf(acc[mt][nt][0] + y0, 0.f), w0, zr[mt*2+0]);
                zr[mt*2+0] = fmaf(fmaxf(acc[mt][nt][1] + y1, 0.f), w1, zr[mt*2+0]);
                zr[mt*2+1] = fmaf(fmaxf(acc[mt][nt][2] + y0, 0.f), w0, zr[mt*2+1]);
                zr[mt*2+1] = fmaf(fmaxf(acc[mt][nt][3] + y1, 0.f), w1, zr[mt*2+1]);
            }
        }
        #pragma unroll
        for (int o = 1; o < 4; o <<= 1) {
            #pragma unroll
            for (int r = 0; r < 4; r++)
                zr[r] += __shfl_xor_sync(0xffffffffu, zr[r], o);
        }
        if (q == 0) {
            const float bias = *sbm2;
            const int base = tile * 32;
            const int rows[4] = {g, g + 8, 16 + g, 24 + g};
            #pragma unroll
            for (int r = 0; r < 4; r++) {
                int orow = base + rows[r];
                if (orow < nrows) out[orow] = zr[r] + bias;
            }
        }
        __syncwarp();
    }
}

// ---------------------------------------------------------------------------
extern "C" void kernel_launch(void* const* d_in, const int* in_sizes, int n_in,
                              void* d_out, int out_size) {
    const float* pos_table = (const float*)d_in[0];
    const float* node_feat = (const float*)d_in[1];
    const float* W1        = (const float*)d_in[2];
    const float* b1        = (const float*)d_in[3];
    const float* W2        = (const float*)d_in[4];
    const float* b2        = (const float*)d_in[5];
    const float* Wm1       = (const float*)d_in[6];
    const float* bm1       = (const float*)d_in[7];
    const float* Wm2       = (const float*)d_in[8];
    const float* bm2       = (const float*)d_in[9];
    const int*   key_idx   = (const int*)d_in[10];
    const int*   node_idx  = (const int*)d_in[11];
    float* out = (float*)d_out;

    const int nrows  = out_size;
    const int ntiles = (nrows + 31) / 32;

    cudaFuncSetAttribute(neurtw_mma,
                         cudaFuncAttributeMaxDynamicSharedMemorySize, SMEM_TOTAL);

    prep_kernel<<<(ENC * D3 + 255) / 256, 256>>>(W2, Wm1, b2, bm1);

    neurtw_mma<<<NBLK, 128, SMEM_TOTAL>>>(pos_table, node_feat, W1, b1, Wm1,
                                          Wm2, bm2, key_idx, node_idx, out,
                                          nrows, ntiles);
}

// round 6
// speedup vs baseline: 2.6185x; 1.4127x over previous
#include <cuda_runtime.h>
#include <cuda_bf16.h>
#include <stdint.h>

#define LP    4
#define ENC   32
#define FEAT  64
#define D3    64
#define NBLK  296
#define WARPS 5
#define THREADS (WARPS * 32)

// X rows: 96 bf16 data + pad -> stride 104 bf16 = 208 B (52 words; 52*r mod 32 distinct for r=0..7)
#define XSTRIDE_B 208
// W rows: 64 bf16 data + pad -> stride 72 bf16 = 144 B (36 words; 36*r mod 32 distinct)
#define WSTRIDE_B 144

// ---- smem layout (bytes) ----
#define OFF_W1   0
#define OFF_B1   512
#define OFF_YB   640
#define OFF_WM2  896
#define OFF_BM2  1152
#define OFF_WH   1280
#define OFF_WL   (OFF_WH + 96 * WSTRIDE_B)              // +13824
#define OFF_XH   (OFF_WL + 96 * WSTRIDE_B)              // +13824
#define OFF_XL   (OFF_XH + WARPS * 32 * XSTRIDE_B)      // +33280
#define SMEM_TOTAL (OFF_XL + WARPS * 32 * XSTRIDE_B)    // 95488

__device__ float g_A[ENC * D3];
__device__ float g_ybias[D3];

// ---------------- helpers ----------------
__device__ __forceinline__ uint32_t smem_u32(const void* p) {
    uint32_t a;
    asm("{ .reg .u64 t; cvta.to.shared.u64 t, %1; cvt.u32.u64 %0, t; }" : "=r"(a) : "l"(p));
    return a;
}
#define LDSM_X4(r0, r1, r2, r3, a) \
    asm volatile("ldmatrix.sync.aligned.m8n8.x4.shared.b16 {%0,%1,%2,%3}, [%4];" \
                 : "=r"(r0), "=r"(r1), "=r"(r2), "=r"(r3) : "r"(a))
#define LDSM_X4_T(r0, r1, r2, r3, a) \
    asm volatile("ldmatrix.sync.aligned.m8n8.x4.trans.shared.b16 {%0,%1,%2,%3}, [%4];" \
                 : "=r"(r0), "=r"(r1), "=r"(r2), "=r"(r3) : "r"(a))
#define MMA16816(d, a0, a1, a2, a3, b0, b1) \
    asm volatile("mma.sync.aligned.m16n8k16.row.col.f32.bf16.bf16.f32 " \
                 "{%0,%1,%2,%3}, {%4,%5,%6,%7}, {%8,%9}, {%0,%1,%2,%3};" \
                 : "+f"((d)[0]), "+f"((d)[1]), "+f"((d)[2]), "+f"((d)[3]) \
                 : "r"(a0), "r"(a1), "r"(a2), "r"(a3), "r"(b0), "r"(b1))
#define PREFETCH_L2(p) asm volatile("prefetch.global.L2 [%0];" :: "l"(p))

__device__ __forceinline__ unsigned pack_bf2(__nv_bfloat16 lo, __nv_bfloat16 hi) {
    return (unsigned)__bfloat16_as_ushort(lo) | ((unsigned)__bfloat16_as_ushort(hi) << 16);
}
__device__ __forceinline__ void split_bf(float x, __nv_bfloat16& h, __nv_bfloat16& l) {
    h = __float2bfloat16_rn(x);
    l = __float2bfloat16_rn(x - __bfloat162float(h));
}

// ---------------------------------------------------------------------------
__global__ void prep_kernel(const float* __restrict__ W2,
                            const float* __restrict__ Wm1,
                            const float* __restrict__ b2,
                            const float* __restrict__ bm1) {
    int t = blockIdx.x * blockDim.x + threadIdx.x;
    if (t < ENC * D3) {
        int k = t >> 6, j = t & 63;
        float s = 0.f;
        #pragma unroll
        for (int e = 0; e < ENC; e++)
            s = fmaf(W2[k * ENC + e], Wm1[e * D3 + j], s);
        g_A[t] = s;
    }
    if (t < D3) {
        float s = bm1[t];
        #pragma unroll
        for (int e = 0; e < ENC; e++)
            s = fmaf(b2[e], Wm1[e * D3 + t], s);
        g_ybias[t] = s;
    }
}

// ---------------------------------------------------------------------------
__global__ __launch_bounds__(THREADS, 2)
void neurtw_mma(const float* __restrict__ pos_table,
                const float* __restrict__ node_feat,
                const float* __restrict__ W1,
                const float* __restrict__ b1,
                const float* __restrict__ Wm1,
                const float* __restrict__ Wm2,
                const float* __restrict__ bm2,
                const int*   __restrict__ key_idx,
                const int*   __restrict__ node_idx,
                float* __restrict__ out,
                int nrows, int ntiles) {
    extern __shared__ __align__(128) char smem[];
    const uint32_t sb = smem_u32(smem);
    const int tid = threadIdx.x, wid = tid >> 5, lane = tid & 31;

    float* sW1  = (float*)(smem + OFF_W1);
    float* sb1a = (float*)(smem + OFF_B1);
    float* sYb  = (float*)(smem + OFF_YB);
    float* sWm2 = (float*)(smem + OFF_WM2);
    float* sbm2 = (float*)(smem + OFF_BM2);

    if (tid < 128) sW1[tid] = W1[tid];
    if (tid < 32)  sb1a[tid] = b1[tid];
    if (tid < 64)  { sYb[tid] = g_ybias[tid]; sWm2[tid] = Wm2[tid]; }
    if (tid == 0)  *sbm2 = bm2[0];

    // stage W (hi/lo split): rows 0..31 from g_A, 32..95 from Wm1 (padded stride)
    for (int t = tid; t < 96 * 64; t += THREADS) {
        int k = t >> 6, n = t & 63;
        float w = (k < ENC) ? g_A[k * D3 + n] : Wm1[k * D3 + n];
        __nv_bfloat16 h, l;
        split_bf(w, h, l);
        *(__nv_bfloat16*)(smem + OFF_WH + k * WSTRIDE_B + n * 2) = h;
        *(__nv_bfloat16*)(smem + OFF_WL + k * WSTRIDE_B + n * 2) = l;
    }
    __syncthreads();

    // ---- per-lane constant ldmatrix addresses (identical to round-4) ----
    const int a_row  = (lane & 7) + 8 * ((lane >> 3) & 1);
    const int a_colb = (lane >> 4) * 16;
    const uint32_t xh_base = sb + OFF_XH + (uint32_t)(wid * 32 + a_row) * XSTRIDE_B + a_colb;
    const uint32_t xl_base = sb + OFF_XL + (uint32_t)(wid * 32 + a_row) * XSTRIDE_B + a_colb;
    const uint32_t b_off = (uint32_t)(((lane & 7) + 8 * ((lane >> 3) & 1)) * WSTRIDE_B
                                      + (lane >> 4) * 16);
    const uint32_t wh_base = sb + OFF_WH + b_off;
    const uint32_t wl_base = sb + OFF_WL + b_off;

    const int gw0 = blockIdx.x * WARPS + wid;
    const int gwstride = NBLK * WARPS;
    const int g = lane >> 2, q4 = lane & 3;

    // own-row indices for first tile
    int key_c = 0, nid_c = 0;
    if (gw0 < ntiles) {
        int rr = gw0 * 32 + lane; if (rr >= nrows) rr = 0;
        key_c = key_idx[rr]; nid_c = node_idx[rr];
    }

    for (int tile = gw0; tile < ntiles; tile += gwstride) {
        // ========== phase 1a: PE hidden layer (own row), split, STS ==========
        {
            const float4 e4 = *(const float4*)(pos_table + (size_t)key_c * LP);
            float h[ENC];
            #pragma unroll
            for (int j = 0; j < ENC; j++) {
                float s = sb1a[j];
                s = fmaf(e4.x, sW1[0 * ENC + j], s);
                s = fmaf(e4.y, sW1[1 * ENC + j], s);
                s = fmaf(e4.z, sW1[2 * ENC + j], s);
                s = fmaf(e4.w, sW1[3 * ENC + j], s);
                h[j] = fmaxf(s, 0.f);
            }
            const int r = wid * 32 + lane;
            char* xh = smem + OFF_XH + r * XSTRIDE_B;
            char* xl = smem + OFF_XL + r * XSTRIDE_B;
            #pragma unroll
            for (int c = 0; c < 4; c++) {
                unsigned hv[4], lv[4];
                #pragma unroll
                for (int u = 0; u < 4; u++) {
                    __nv_bfloat16 a0, l0, a1, l1;
                    split_bf(h[c * 8 + 2 * u],     a0, l0);
                    split_bf(h[c * 8 + 2 * u + 1], a1, l1);
                    hv[u] = pack_bf2(a0, a1);
                    lv[u] = pack_bf2(l0, l1);
                }
                *(uint4*)(xh + c * 16) = make_uint4(hv[0], hv[1], hv[2], hv[3]);
                *(uint4*)(xl + c * 16) = make_uint4(lv[0], lv[1], lv[2], lv[3]);
            }
        }
        // ========== phase 1b: coalesced cooperative feat gather ==========
        // 16 lanes per row; lane -> float4 chunk qq (0..15); 16 iters cover 32 rows.
        {
            const int sub = lane >> 4;        // 0..1
            const int qq  = lane & 15;        // float4 index within row
            #pragma unroll
            for (int i = 0; i < 16; i++) {
                const int riw = 2 * i + sub;  // row-in-warp 0..31
                const int nidr = __shfl_sync(0xffffffffu, nid_c, riw);
                const float4 fv = __ldg((const float4*)(node_feat + (size_t)nidr * FEAT) + qq);
                __nv_bfloat16 a0, l0, a1, l1, a2, l2, a3, l3;
                split_bf(fv.x, a0, l0); split_bf(fv.y, a1, l1);
                split_bf(fv.z, a2, l2); split_bf(fv.w, a3, l3);
                const int off = (wid * 32 + riw) * XSTRIDE_B + 64 + 8 * qq;
                *(uint2*)(smem + OFF_XH + off) = make_uint2(pack_bf2(a0, a1), pack_bf2(a2, a3));
                *(uint2*)(smem + OFF_XL + off) = make_uint2(pack_bf2(l0, l1), pack_bf2(l2, l3));
            }
        }
        __syncwarp();

        // ---- prefetch next tile to L2 (no parked registers) ----
        {
            const int nt = tile + gwstride;
            if (nt < ntiles) {
                int rr = nt * 32 + lane; if (rr >= nrows) rr = 0;
                key_c = key_idx[rr]; nid_c = node_idx[rr];
                const char* pp = (const char*)(pos_table + (size_t)key_c * LP);
                const char* fp = (const char*)(node_feat + (size_t)nid_c * FEAT);
                PREFETCH_L2(pp);
                PREFETCH_L2(fp);
                PREFETCH_L2(fp + 128);
            }
        }

        // ========== phase 2: 3-pass split-bf16 MMA (round-4 verbatim) ==========
        float acc[2][8][4];
        #pragma unroll
        for (int mt = 0; mt < 2; mt++)
            #pragma unroll
            for (int nt = 0; nt < 8; nt++)
                #pragma unroll
                for (int c = 0; c < 4; c++) acc[mt][nt][c] = 0.f;

        #pragma unroll
        for (int kc = 0; kc < 6; kc++) {
            const uint32_t akoff = (uint32_t)(kc * 32);
            const uint32_t bkoff = (uint32_t)(kc * 16 * WSTRIDE_B);
            uint32_t ah[2][4], al[2][4];
            LDSM_X4(ah[0][0], ah[0][1], ah[0][2], ah[0][3], xh_base + akoff);
            LDSM_X4(ah[1][0], ah[1][1], ah[1][2], ah[1][3], xh_base + 16 * XSTRIDE_B + akoff);
            LDSM_X4(al[0][0], al[0][1], al[0][2], al[0][3], xl_base + akoff);
            LDSM_X4(al[1][0], al[1][1], al[1][2], al[1][3], xl_base + 16 * XSTRIDE_B + akoff);

            uint32_t bh[8][2], bl[8][2];
            #pragma unroll
            for (int ng = 0; ng < 4; ng++) {
                uint32_t r0, r1, r2, r3;
                LDSM_X4_T(r0, r1, r2, r3, wh_base + bkoff + (uint32_t)(ng * 32));
                bh[2*ng][0] = r0; bh[2*ng][1] = r1; bh[2*ng+1][0] = r2; bh[2*ng+1][1] = r3;
                LDSM_X4_T(r0, r1, r2, r3, wl_base + bkoff + (uint32_t)(ng * 32));
                bl[2*ng][0] = r0; bl[2*ng][1] = r1; bl[2*ng+1][0] = r2; bl[2*ng+1][1] = r3;
            }
            #pragma unroll
            for (int mt = 0; mt < 2; mt++) {
                #pragma unroll
                for (int nt = 0; nt < 8; nt++) {
                    MMA16816(acc[mt][nt], ah[mt][0], ah[mt][1], ah[mt][2], ah[mt][3],
                             bh[nt][0], bh[nt][1]);
                    MMA16816(acc[mt][nt], ah[mt][0], ah[mt][1], ah[mt][2], ah[mt][3],
                             bl[nt][0], bl[nt][1]);
                    MMA16816(acc[mt][nt], al[mt][0], al[mt][1], al[mt][2], al[mt][3],
                             bh[nt][0], bh[nt][1]);
                }
            }
        }

        // ========== phase 3: bias+relu+Wm2 dot, reduce, store ==========
        float zr[4] = {0.f, 0.f, 0.f, 0.f};
        #pragma unroll
        for (int mt = 0; mt < 2; mt++) {
            #pragma unroll
            for (int nt = 0; nt < 8; nt++) {
                const int c0 = nt * 8 + 2 * q4;
                const float y0 = sYb[c0], y1 = sYb[c0 + 1];
                const float w0 = sWm2[c0], w1 = sWm2[c0 + 1];
                zr[mt*2+0] = fmaf(fmaxf(acc[mt][nt][0] + y0, 0.f), w0, zr[mt*2+0]);
                zr[mt*2+0] = fmaf(fmaxf(acc[mt][nt][1] + y1, 0.f), w1, zr[mt*2+0]);
                zr[mt*2+1] = fmaf(fmaxf(acc[mt][nt][2] + y0, 0.f), w0, zr[mt*2+1]);
                zr[mt*2+1] = fmaf(fmaxf(acc[mt][nt][3] + y1, 0.f), w1, zr[mt*2+1]);
            }
        }
        #pragma unroll
        for (int o = 1; o < 4; o <<= 1) {
            #pragma unroll
            for (int r = 0; r < 4; r++)
                zr[r] += __shfl_xor_sync(0xffffffffu, zr[r], o);
        }
        if (q4 == 0) {
            const float bias = *sbm2;
            const int base = tile * 32;
            const int rows[4] = {g, g + 8, 16 + g, 24 + g};
            #pragma unroll
            for (int r = 0; r < 4; r++) {
                int orow = base + rows[r];
                if (orow < nrows) out[orow] = zr[r] + bias;
            }
        }
        __syncwarp();
    }
}

// ---------------------------------------------------------------------------
extern "C" void kernel_launch(void* const* d_in, const int* in_sizes, int n_in,
                              void* d_out, int out_size) {
    const float* pos_table = (const float*)d_in[0];
    const float* node_feat = (const float*)d_in[1];
    const float* W1        = (const float*)d_in[2];
    const float* b1        = (const float*)d_in[3];
    const float* W2        = (const float*)d_in[4];
    const float* b2        = (const float*)d_in[5];
    const float* Wm1       = (const float*)d_in[6];
    const float* bm1       = (const float*)d_in[7];
    const float* Wm2       = (const float*)d_in[8];
    const float* bm2       = (const float*)d_in[9];
    const int*   key_idx   = (const int*)d_in[10];
    const int*   node_idx  = (const int*)d_in[11];
    float* out = (float*)d_out;

    const int nrows  = out_size;
    const int ntiles = (nrows + 31) / 32;

    cudaFuncSetAttribute(neurtw_mma,
                         cudaFuncAttributeMaxDynamicSharedMemorySize, SMEM_TOTAL);

    prep_kernel<<<(ENC * D3 + 255) / 256, 256>>>(W2, Wm1, b2, bm1);

    neurtw_mma<<<NBLK, THREADS, SMEM_TOTAL>>>(pos_table, node_feat, W1, b1, Wm1,
                                              Wm2, bm2, key_idx, node_idx, out,
                                              nrows, ntiles);
}

// round 7
// speedup vs baseline: 4.3418x; 1.6582x over previous
#include <cuda_runtime.h>
#include <cuda_fp16.h>
#include <stdint.h>

#define LP    4
#define ENC   32
#define FEAT  64
#define D3    64
#define NBLK  296
#define WARPS 7
#define THREADS (WARPS * 32)

// X rows: 96 fp16 data + pad -> stride 208 B (52 words; 52*r mod 32 distinct for r=0..7)
#define XSTRIDE_B 208
// W rows: 64 fp16 data + pad -> stride 144 B (36 words; 36*r mod 32 distinct)
#define WSTRIDE_B 144

// ---- smem layout (bytes) ----
#define OFF_W1   0
#define OFF_B1   512
#define OFF_YB   640
#define OFF_WM2  896
#define OFF_BM2  1152
#define OFF_WH   1280
#define OFF_WL   (OFF_WH + 96 * WSTRIDE_B)              // +13824
#define OFF_XH   (OFF_WL + 96 * WSTRIDE_B)              // +13824
#define SMEM_TOTAL (OFF_XH + WARPS * 32 * XSTRIDE_B)    // 75520

__device__ float g_A[ENC * D3];
__device__ float g_ybias[D3];

// ---------------- helpers ----------------
__device__ __forceinline__ uint32_t smem_u32(const void* p) {
    uint32_t a;
    asm("{ .reg .u64 t; cvta.to.shared.u64 t, %1; cvt.u32.u64 %0, t; }" : "=r"(a) : "l"(p));
    return a;
}
#define LDSM_X4(r0, r1, r2, r3, a) \
    asm volatile("ldmatrix.sync.aligned.m8n8.x4.shared.b16 {%0,%1,%2,%3}, [%4];" \
                 : "=r"(r0), "=r"(r1), "=r"(r2), "=r"(r3) : "r"(a))
#define LDSM_X4_T(r0, r1, r2, r3, a) \
    asm volatile("ldmatrix.sync.aligned.m8n8.x4.trans.shared.b16 {%0,%1,%2,%3}, [%4];" \
                 : "=r"(r0), "=r"(r1), "=r"(r2), "=r"(r3) : "r"(a))
#define MMA16816H(d, a0, a1, a2, a3, b0, b1) \
    asm volatile("mma.sync.aligned.m16n8k16.row.col.f32.f16.f16.f32 " \
                 "{%0,%1,%2,%3}, {%4,%5,%6,%7}, {%8,%9}, {%0,%1,%2,%3};" \
                 : "+f"((d)[0]), "+f"((d)[1]), "+f"((d)[2]), "+f"((d)[3]) \
                 : "r"(a0), "r"(a1), "r"(a2), "r"(a3), "r"(b0), "r"(b1))
#define PREFETCH_L2(p) asm volatile("prefetch.global.L2 [%0];" :: "l"(p))

__device__ __forceinline__ unsigned pack_h2(float a, float b) {
    __half2 h2 = __floats2half2_rn(a, b);
    return *(unsigned*)&h2;
}

// ---------------------------------------------------------------------------
__global__ void prep_kernel(const float* __restrict__ W2,
                            const float* __restrict__ Wm1,
                            const float* __restrict__ b2,
                            const float* __restrict__ bm1) {
    int t = blockIdx.x * blockDim.x + threadIdx.x;
    if (t < ENC * D3) {
        int k = t >> 6, j = t & 63;
        float s = 0.f;
        #pragma unroll
        for (int e = 0; e < ENC; e++)
            s = fmaf(W2[k * ENC + e], Wm1[e * D3 + j], s);
        g_A[t] = s;
    }
    if (t < D3) {
        float s = bm1[t];
        #pragma unroll
        for (int e = 0; e < ENC; e++)
            s = fmaf(b2[e], Wm1[e * D3 + t], s);
        g_ybias[t] = s;
    }
}

// ---------------------------------------------------------------------------
__global__ __launch_bounds__(THREADS, 2)
void neurtw_mma(const float* __restrict__ pos_table,
                const float* __restrict__ node_feat,
                const float* __restrict__ W1,
                const float* __restrict__ b1,
                const float* __restrict__ Wm1,
                const float* __restrict__ Wm2,
                const float* __restrict__ bm2,
                const int*   __restrict__ key_idx,
                const int*   __restrict__ node_idx,
                float* __restrict__ out,
                int nrows, int ntiles) {
    extern __shared__ __align__(128) char smem[];
    const uint32_t sb = smem_u32(smem);
    const int tid = threadIdx.x, wid = tid >> 5, lane = tid & 31;

    float* sW1  = (float*)(smem + OFF_W1);
    float* sb1a = (float*)(smem + OFF_B1);
    float* sYb  = (float*)(smem + OFF_YB);
    float* sWm2 = (float*)(smem + OFF_WM2);
    float* sbm2 = (float*)(smem + OFF_BM2);

    if (tid < 128) sW1[tid] = W1[tid];
    if (tid < 32)  sb1a[tid] = b1[tid];
    if (tid < 64)  { sYb[tid] = g_ybias[tid]; sWm2[tid] = Wm2[tid]; }
    if (tid == 0)  *sbm2 = bm2[0];

    // stage W split into fp16 hi + fp16 lo (exact to ~2^-22; lo may be subnormal)
    for (int t = tid; t < 96 * 64; t += THREADS) {
        int k = t >> 6, n = t & 63;
        float w = (k < ENC) ? g_A[k * D3 + n] : Wm1[k * D3 + n];
        __half h = __float2half_rn(w);
        __half l = __float2half_rn(w - __half2float(h));
        *(__half*)(smem + OFF_WH + k * WSTRIDE_B + n * 2) = h;
        *(__half*)(smem + OFF_WL + k * WSTRIDE_B + n * 2) = l;
    }
    __syncthreads();

    // ---- per-lane constant ldmatrix addresses ----
    const int a_row  = (lane & 7) + 8 * ((lane >> 3) & 1);
    const int a_colb = (lane >> 4) * 16;
    const uint32_t xh_base = sb + OFF_XH + (uint32_t)(wid * 32 + a_row) * XSTRIDE_B + a_colb;
    const uint32_t b_off = (uint32_t)(((lane & 7) + 8 * ((lane >> 3) & 1)) * WSTRIDE_B
                                      + (lane >> 4) * 16);
    const uint32_t wh_base = sb + OFF_WH + b_off;
    const uint32_t wl_base = sb + OFF_WL + b_off;

    const int gw0 = blockIdx.x * WARPS + wid;
    const int gwstride = NBLK * WARPS;
    const int g = lane >> 2, q4 = lane & 3;

    int key_c = 0, nid_c = 0;
    if (gw0 < ntiles) {
        int rr = gw0 * 32 + lane; if (rr >= nrows) rr = 0;
        key_c = key_idx[rr]; nid_c = node_idx[rr];
    }

    for (int tile = gw0; tile < ntiles; tile += gwstride) {
        // ========== phase 1a: PE hidden layer (own row), fp16, STS ==========
        {
            const float4 e4 = *(const float4*)(pos_table + (size_t)key_c * LP);
            float h[ENC];
            #pragma unroll
            for (int j = 0; j < ENC; j++) {
                float s = sb1a[j];
                s = fmaf(e4.x, sW1[0 * ENC + j], s);
                s = fmaf(e4.y, sW1[1 * ENC + j], s);
                s = fmaf(e4.z, sW1[2 * ENC + j], s);
                s = fmaf(e4.w, sW1[3 * ENC + j], s);
                h[j] = fmaxf(s, 0.f);
            }
            char* xh = smem + OFF_XH + (wid * 32 + lane) * XSTRIDE_B;
            #pragma unroll
            for (int c = 0; c < 4; c++) {
                unsigned hv[4];
                #pragma unroll
                for (int u = 0; u < 4; u++)
                    hv[u] = pack_h2(h[c * 8 + 2 * u], h[c * 8 + 2 * u + 1]);
                *(uint4*)(xh + c * 16) = make_uint4(hv[0], hv[1], hv[2], hv[3]);
            }
        }
        // ========== phase 1b: coalesced cooperative feat gather ==========
        {
            const int sub = lane >> 4;        // 0..1
            const int qq  = lane & 15;        // float4 index within row
            #pragma unroll
            for (int i = 0; i < 16; i++) {
                const int riw = 2 * i + sub;  // row-in-warp 0..31
                const int nidr = __shfl_sync(0xffffffffu, nid_c, riw);
                const float4 fv = __ldg((const float4*)(node_feat + (size_t)nidr * FEAT) + qq);
                const int off = (wid * 32 + riw) * XSTRIDE_B + 64 + 8 * qq;
                *(uint2*)(smem + OFF_XH + off) =
                    make_uint2(pack_h2(fv.x, fv.y), pack_h2(fv.z, fv.w));
            }
        }
        __syncwarp();

        // ---- prefetch next tile to L2 ----
        {
            const int nt = tile + gwstride;
            if (nt < ntiles) {
                int rr = nt * 32 + lane; if (rr >= nrows) rr = 0;
                key_c = key_idx[rr]; nid_c = node_idx[rr];
                const char* pp = (const char*)(pos_table + (size_t)key_c * LP);
                const char* fp = (const char*)(node_feat + (size_t)nid_c * FEAT);
                PREFETCH_L2(pp);
                PREFETCH_L2(fp);
                PREFETCH_L2(fp + 128);
            }
        }

        // ========== phase 2: 2-pass fp16 MMA (Xh*Wh + Xh*Wl) ==========
        float acc[2][8][4];
        #pragma unroll
        for (int mt = 0; mt < 2; mt++)
            #pragma unroll
            for (int nt = 0; nt < 8; nt++)
                #pragma unroll
                for (int c = 0; c < 4; c++) acc[mt][nt][c] = 0.f;

        #pragma unroll
        for (int kc = 0; kc < 6; kc++) {
            const uint32_t akoff = (uint32_t)(kc * 32);
            const uint32_t bkoff = (uint32_t)(kc * 16 * WSTRIDE_B);
            uint32_t ah[2][4];
            LDSM_X4(ah[0][0], ah[0][1], ah[0][2], ah[0][3], xh_base + akoff);
            LDSM_X4(ah[1][0], ah[1][1], ah[1][2], ah[1][3], xh_base + 16 * XSTRIDE_B + akoff);

            uint32_t bh[8][2], bl[8][2];
            #pragma unroll
            for (int ng = 0; ng < 4; ng++) {
                uint32_t r0, r1, r2, r3;
                LDSM_X4_T(r0, r1, r2, r3, wh_base + bkoff + (uint32_t)(ng * 32));
                bh[2*ng][0] = r0; bh[2*ng][1] = r1; bh[2*ng+1][0] = r2; bh[2*ng+1][1] = r3;
                LDSM_X4_T(r0, r1, r2, r3, wl_base + bkoff + (uint32_t)(ng * 32));
                bl[2*ng][0] = r0; bl[2*ng][1] = r1; bl[2*ng+1][0] = r2; bl[2*ng+1][1] = r3;
            }
            #pragma unroll
            for (int mt = 0; mt < 2; mt++) {
                #pragma unroll
                for (int nt = 0; nt < 8; nt++) {
                    MMA16816H(acc[mt][nt], ah[mt][0], ah[mt][1], ah[mt][2], ah[mt][3],
                              bh[nt][0], bh[nt][1]);
                    MMA16816H(acc[mt][nt], ah[mt][0], ah[mt][1], ah[mt][2], ah[mt][3],
                              bl[nt][0], bl[nt][1]);
                }
            }
        }

        // ========== phase 3: bias+relu+Wm2 dot, reduce, store ==========
        float zr[4] = {0.f, 0.f, 0.f, 0.f};
        #pragma unroll
        for (int mt = 0; mt < 2; mt++) {
            #pragma unroll
            for (int nt = 0; nt < 8; nt++) {
                const int c0 = nt * 8 + 2 * q4;
                const float y0 = sYb[c0], y1 = sYb[c0 + 1];
                const float w0 = sWm2[c0], w1 = sWm2[c0 + 1];
                zr[mt*2+0] = fmaf(fmaxf(acc[mt][nt][0] + y0, 0.f), w0, zr[mt*2+0]);
                zr[mt*2+0] = fmaf(fmaxf(acc[mt][nt][1] + y1, 0.f), w1, zr[mt*2+0]);
                zr[mt*2+1] = fmaf(fmaxf(acc[mt][nt][2] + y0, 0.f), w0, zr[mt*2+1]);
                zr[mt*2+1] = fmaf(fmaxf(acc[mt][nt][3] + y1, 0.f), w1, zr[mt*2+1]);
            }
        }
        #pragma unroll
        for (int o = 1; o < 4; o <<= 1) {
            #pragma unroll
            for (int r = 0; r < 4; r++)
                zr[r] += __shfl_xor_sync(0xffffffffu, zr[r], o);
        }
        if (q4 == 0) {
            const float bias = *sbm2;
            const int base = tile * 32;
            const int rows[4] = {g, g + 8, 16 + g, 24 + g};
            #pragma unroll
            for (int r = 0; r < 4; r++) {
                int orow = base + rows[r];
                if (orow < nrows) out[orow] = zr[r] + bias;
            }
        }
        __syncwarp();
    }
}

// ---------------------------------------------------------------------------
extern "C" void kernel_launch(void* const* d_in, const int* in_sizes, int n_in,
                              void* d_out, int out_size) {
    const float* pos_table = (const float*)d_in[0];
    const float* node_feat = (const float*)d_in[1];
    const float* W1        = (const float*)d_in[2];
    const float* b1        = (const float*)d_in[3];
    const float* W2        = (const float*)d_in[4];
    const float* b2        = (const float*)d_in[5];
    const float* Wm1       = (const float*)d_in[6];
    const float* bm1       = (const float*)d_in[7];
    const float* Wm2       = (const float*)d_in[8];
    const float* bm2       = (const float*)d_in[9];
    const int*   key_idx   = (const int*)d_in[10];
    const int*   node_idx  = (const int*)d_in[11];
    float* out = (float*)d_out;

    const int nrows  = out_size;
    const int ntiles = (nrows + 31) / 32;

    cudaFuncSetAttribute(neurtw_mma,
                         cudaFuncAttributeMaxDynamicSharedMemorySize, SMEM_TOTAL);

    prep_kernel<<<(ENC * D3 + 255) / 256, 256>>>(W2, Wm1, b2, bm1);

    neurtw_mma<<<NBLK, THREADS, SMEM_TOTAL>>>(pos_table, node_feat, W1, b1, Wm1,
                                              Wm2, bm2, key_idx, node_idx, out,
                                              nrows, ntiles);
}

// round 8
// speedup vs baseline: 6.0822x; 1.4008x over previous
#include <cuda_runtime.h>
#include <cuda_fp16.h>
#include <stdint.h>

#define LP    4
#define ENC   32
#define FEAT  64
#define D3    64
#define NBLK  296
#define WARPS 8
#define THREADS (WARPS * 32)

// X rows: 96 fp16 data + pad -> stride 208 B (52 words; 52*r mod 32 distinct for r=0..7)
#define XSTRIDE_B 208
// W rows: 64 fp16 data + pad -> stride 144 B (36 words; 36*r mod 32 distinct)
#define WSTRIDE_B 144

// ---- smem layout (bytes) ----
#define OFF_W1   0
#define OFF_B1   512
#define OFF_YB   640
#define OFF_WM2  896
#define OFF_BM2  1152
#define OFF_WH   1280
#define OFF_XH   (OFF_WH + 96 * WSTRIDE_B)              // +13824 -> 15104
#define SMEM_TOTAL (OFF_XH + WARPS * 32 * XSTRIDE_B)    // 68352

__device__ float g_A[ENC * D3];
__device__ float g_ybias[D3];

// ---------------- helpers ----------------
__device__ __forceinline__ uint32_t smem_u32(const void* p) {
    uint32_t a;
    asm("{ .reg .u64 t; cvta.to.shared.u64 t, %1; cvt.u32.u64 %0, t; }" : "=r"(a) : "l"(p));
    return a;
}
#define LDSM_X4(r0, r1, r2, r3, a) \
    asm volatile("ldmatrix.sync.aligned.m8n8.x4.shared.b16 {%0,%1,%2,%3}, [%4];" \
                 : "=r"(r0), "=r"(r1), "=r"(r2), "=r"(r3) : "r"(a))
#define LDSM_X4_T(r0, r1, r2, r3, a) \
    asm volatile("ldmatrix.sync.aligned.m8n8.x4.trans.shared.b16 {%0,%1,%2,%3}, [%4];" \
                 : "=r"(r0), "=r"(r1), "=r"(r2), "=r"(r3) : "r"(a))
#define MMA16816H(d, a0, a1, a2, a3, b0, b1) \
    asm volatile("mma.sync.aligned.m16n8k16.row.col.f32.f16.f16.f32 " \
                 "{%0,%1,%2,%3}, {%4,%5,%6,%7}, {%8,%9}, {%0,%1,%2,%3};" \
                 : "+f"((d)[0]), "+f"((d)[1]), "+f"((d)[2]), "+f"((d)[3]) \
                 : "r"(a0), "r"(a1), "r"(a2), "r"(a3), "r"(b0), "r"(b1))
#define PREFETCH_L2(p) asm volatile("prefetch.global.L2 [%0];" :: "l"(p))

__device__ __forceinline__ unsigned pack_h2(float a, float b) {
    __half2 h2 = __floats2half2_rn(a, b);
    return *(unsigned*)&h2;
}

// ---------------------------------------------------------------------------
__global__ void prep_kernel(const float* __restrict__ W2,
                            const float* __restrict__ Wm1,
                            const float* __restrict__ b2,
                            const float* __restrict__ bm1) {
    int t = blockIdx.x * blockDim.x + threadIdx.x;
    if (t < ENC * D3) {
        int k = t >> 6, j = t & 63;
        float s = 0.f;
        #pragma unroll
        for (int e = 0; e < ENC; e++)
            s = fmaf(W2[k * ENC + e], Wm1[e * D3 + j], s);
        g_A[t] = s;
    }
    if (t < D3) {
        float s = bm1[t];
        #pragma unroll
        for (int e = 0; e < ENC; e++)
            s = fmaf(b2[e], Wm1[e * D3 + t], s);
        g_ybias[t] = s;
    }
}

// ---------------------------------------------------------------------------
__global__ __launch_bounds__(THREADS, 2)
void neurtw_mma(const float* __restrict__ pos_table,
                const float* __restrict__ node_feat,
                const float* __restrict__ W1,
                const float* __restrict__ b1,
                const float* __restrict__ Wm1,
                const float* __restrict__ Wm2,
                const float* __restrict__ bm2,
                const int*   __restrict__ key_idx,
                const int*   __restrict__ node_idx,
                float* __restrict__ out,
                int nrows, int ntiles) {
    extern __shared__ __align__(128) char smem[];
    const uint32_t sb = smem_u32(smem);
    const int tid = threadIdx.x, wid = tid >> 5, lane = tid & 31;

    float* sW1  = (float*)(smem + OFF_W1);
    float* sb1a = (float*)(smem + OFF_B1);
    float* sYb  = (float*)(smem + OFF_YB);
    float* sWm2 = (float*)(smem + OFF_WM2);
    float* sbm2 = (float*)(smem + OFF_BM2);

    if (tid < 128) sW1[tid] = W1[tid];
    if (tid < 32)  sb1a[tid] = b1[tid];
    if (tid < 64)  { sYb[tid] = g_ybias[tid]; sWm2[tid] = Wm2[tid]; }
    if (tid == 0)  *sbm2 = bm2[0];

    // stage W in single fp16 (rounded; error ~2^-11 rel, same magnitude as X rounding)
    for (int t = tid; t < 96 * 64; t += THREADS) {
        int k = t >> 6, n = t & 63;
        float w = (k < ENC) ? g_A[k * D3 + n] : Wm1[k * D3 + n];
        *(__half*)(smem + OFF_WH + k * WSTRIDE_B + n * 2) = __float2half_rn(w);
    }
    __syncthreads();

    // ---- per-lane constant ldmatrix addresses ----
    const int a_row  = (lane & 7) + 8 * ((lane >> 3) & 1);
    const int a_colb = (lane >> 4) * 16;
    const uint32_t xh_base = sb + OFF_XH + (uint32_t)(wid * 32 + a_row) * XSTRIDE_B + a_colb;
    const uint32_t b_off = (uint32_t)(((lane & 7) + 8 * ((lane >> 3) & 1)) * WSTRIDE_B
                                      + (lane >> 4) * 16);
    const uint32_t wh_base = sb + OFF_WH + b_off;

    const int gw0 = blockIdx.x * WARPS + wid;
    const int gwstride = NBLK * WARPS;
    const int g = lane >> 2, q4 = lane & 3;

    int key_c = 0, nid_c = 0;
    if (gw0 < ntiles) {
        int rr = gw0 * 32 + lane; if (rr >= nrows) rr = 0;
        key_c = key_idx[rr]; nid_c = node_idx[rr];
    }

    for (int tile = gw0; tile < ntiles; tile += gwstride) {
        // ========== phase 1a: PE hidden layer (own row), fp16, STS ==========
        {
            const float4 e4 = *(const float4*)(pos_table + (size_t)key_c * LP);
            float h[ENC];
            #pragma unroll
            for (int j = 0; j < ENC; j++) {
                float s = sb1a[j];
                s = fmaf(e4.x, sW1[0 * ENC + j], s);
                s = fmaf(e4.y, sW1[1 * ENC + j], s);
                s = fmaf(e4.z, sW1[2 * ENC + j], s);
                s = fmaf(e4.w, sW1[3 * ENC + j], s);
                h[j] = fmaxf(s, 0.f);
            }
            char* xh = smem + OFF_XH + (wid * 32 + lane) * XSTRIDE_B;
            #pragma unroll
            for (int c = 0; c < 4; c++) {
                unsigned hv[4];
                #pragma unroll
                for (int u = 0; u < 4; u++)
                    hv[u] = pack_h2(h[c * 8 + 2 * u], h[c * 8 + 2 * u + 1]);
                *(uint4*)(xh + c * 16) = make_uint4(hv[0], hv[1], hv[2], hv[3]);
            }
        }
        // ========== phase 1b: coalesced cooperative feat gather ==========
        {
            const int sub = lane >> 4;        // 0..1
            const int qq  = lane & 15;        // float4 index within row
            #pragma unroll
            for (int i = 0; i < 16; i++) {
                const int riw = 2 * i + sub;  // row-in-warp 0..31
                const int nidr = __shfl_sync(0xffffffffu, nid_c, riw);
                const float4 fv = __ldg((const float4*)(node_feat + (size_t)nidr * FEAT) + qq);
                const int off = (wid * 32 + riw) * XSTRIDE_B + 64 + 8 * qq;
                *(uint2*)(smem + OFF_XH + off) =
                    make_uint2(pack_h2(fv.x, fv.y), pack_h2(fv.z, fv.w));
            }
        }
        __syncwarp();

        // ---- prefetch next tile to L2 ----
        {
            const int nt = tile + gwstride;
            if (nt < ntiles) {
                int rr = nt * 32 + lane; if (rr >= nrows) rr = 0;
                key_c = key_idx[rr]; nid_c = node_idx[rr];
                const char* pp = (const char*)(pos_table + (size_t)key_c * LP);
                const char* fp = (const char*)(node_feat + (size_t)nid_c * FEAT);
                PREFETCH_L2(pp);
                PREFETCH_L2(fp);
                PREFETCH_L2(fp + 128);
            }
        }

        // ========== phase 2: single-pass fp16 MMA ==========
        float acc[2][8][4];
        #pragma unroll
        for (int mt = 0; mt < 2; mt++)
            #pragma unroll
            for (int nt = 0; nt < 8; nt++)
                #pragma unroll
                for (int c = 0; c < 4; c++) acc[mt][nt][c] = 0.f;

        #pragma unroll
        for (int kc = 0; kc < 6; kc++) {
            const uint32_t akoff = (uint32_t)(kc * 32);
            const uint32_t bkoff = (uint32_t)(kc * 16 * WSTRIDE_B);
            uint32_t ah[2][4];
            LDSM_X4(ah[0][0], ah[0][1], ah[0][2], ah[0][3], xh_base + akoff);
            LDSM_X4(ah[1][0], ah[1][1], ah[1][2], ah[1][3], xh_base + 16 * XSTRIDE_B + akoff);

            uint32_t bh[8][2];
            #pragma unroll
            for (int ng = 0; ng < 4; ng++) {
                uint32_t r0, r1, r2, r3;
                LDSM_X4_T(r0, r1, r2, r3, wh_base + bkoff + (uint32_t)(ng * 32));
                bh[2*ng][0] = r0; bh[2*ng][1] = r1; bh[2*ng+1][0] = r2; bh[2*ng+1][1] = r3;
            }
            #pragma unroll
            for (int mt = 0; mt < 2; mt++) {
                #pragma unroll
                for (int nt = 0; nt < 8; nt++) {
                    MMA16816H(acc[mt][nt], ah[mt][0], ah[mt][1], ah[mt][2], ah[mt][3],
                              bh[nt][0], bh[nt][1]);
                }
            }
        }

        // ========== phase 3: bias+relu+Wm2 dot, reduce, store ==========
        float zr[4] = {0.f, 0.f, 0.f, 0.f};
        #pragma unroll
        for (int mt = 0; mt < 2; mt++) {
            #pragma unroll
            for (int nt = 0; nt < 8; nt++) {
                const int c0 = nt * 8 + 2 * q4;
                const float y0 = sYb[c0], y1 = sYb[c0 + 1];
                const float w0 = sWm2[c0], w1 = sWm2[c0 + 1];
                zr[mt*2+0] = fmaf(fmaxf(acc[mt][nt][0] + y0, 0.f), w0, zr[mt*2+0]);
                zr[mt*2+0] = fmaf(fmaxf(acc[mt][nt][1] + y1, 0.f), w1, zr[mt*2+0]);
                zr[mt*2+1] = fmaf(fmaxf(acc[mt][nt][2] + y0, 0.f), w0, zr[mt*2+1]);
                zr[mt*2+1] = fmaf(fmaxf(acc[mt][nt][3] + y1, 0.f), w1, zr[mt*2+1]);
            }
        }
        #pragma unroll
        for (int o = 1; o < 4; o <<= 1) {
            #pragma unroll
            for (int r = 0; r < 4; r++)
                zr[r] += __shfl_xor_sync(0xffffffffu, zr[r], o);
        }
        if (q4 == 0) {
            const float bias = *sbm2;
            const int base = tile * 32;
            const int rows[4] = {g, g + 8, 16 + g, 24 + g};
            #pragma unroll
            for (int r = 0; r < 4; r++) {
                int orow = base + rows[r];
                if (orow < nrows) out[orow] = zr[r] + bias;
            }
        }
        __syncwarp();
    }
}

// ---------------------------------------------------------------------------
extern "C" void kernel_launch(void* const* d_in, const int* in_sizes, int n_in,
                              void* d_out, int out_size) {
    const float* pos_table = (const float*)d_in[0];
    const float* node_feat = (const float*)d_in[1];
    const float* W1        = (const float*)d_in[2];
    const float* b1        = (const float*)d_in[3];
    const float* W2        = (const float*)d_in[4];
    const float* b2        = (const float*)d_in[5];
    const float* Wm1       = (const float*)d_in[6];
    const float* bm1       = (const float*)d_in[7];
    const float* Wm2       = (const float*)d_in[8];
    const float* bm2       = (const float*)d_in[9];
    const int*   key_idx   = (const int*)d_in[10];
    const int*   node_idx  = (const int*)d_in[11];
    float* out = (float*)d_out;

    const int nrows  = out_size;
    const int ntiles = (nrows + 31) / 32;

    cudaFuncSetAttribute(neurtw_mma,
                         cudaFuncAttributeMaxDynamicSharedMemorySize, SMEM_TOTAL);

    prep_kernel<<<(ENC * D3 + 255) / 256, 256>>>(W2, Wm1, b2, bm1);

    neurtw_mma<<<NBLK, THREADS, SMEM_TOTAL>>>(pos_table, node_feat, W1, b1, Wm1,
                                              Wm2, bm2, key_idx, node_idx, out,
                                              nrows, ntiles);
}